// round 3
// baseline (speedup 1.0000x reference)
#include <cuda_runtime.h>
#include <math.h>

#define Bn 512
#define Tn 512
#define Hn 512
#define GT 32          // hidden-slice tiles
#define BT 4           // batch tiles
#define JS 16          // hidden units per block  (Hn/GT)
#define BS 128         // batch rows per block    (Bn/BT)
#define NBLK (GT*BT)   // 128 blocks, all co-resident on 148 SMs
#define NTHR 512
#define W_STRIDE 68    // 64 gate-cols padded; k-row stride (floats)
#define H_STRIDE 132   // 128 batch padded; k-row stride (floats)

// Scratch (no cudaMalloc allowed): h ping-pong stored TRANSPOSED [hidden][batch]
__device__ float g_h[2][Hn][Bn];
__device__ float g_seqT[Tn][Bn];
__device__ unsigned g_count = 0;
__device__ volatile unsigned g_gen = 0;

__device__ __forceinline__ void grid_sync(unsigned target) {
    __syncthreads();
    if (threadIdx.x == 0) {
        __threadfence();
        unsigned old = atomicAdd(&g_count, 1u);
        if (old == NBLK - 1) {
            g_count = 0;          // reset for next barrier
            __threadfence();
            g_gen = target;       // release (volatile store)
        } else {
            while (g_gen != target) { }
            __threadfence();      // acquire
        }
    }
    __syncthreads();
}

__device__ __forceinline__ float sigf(float x) { return 1.0f / (1.0f + expf(-x)); }

__global__ __launch_bounds__(NTHR, 1)
void lstm_persistent(const float* __restrict__ seq,
                     const float* __restrict__ Wih,
                     const float* __restrict__ Whh,
                     const float* __restrict__ bih,
                     const float* __restrict__ bhh)
{
    extern __shared__ float smem[];
    float* w_s    = smem;                      // [512][W_STRIDE] : W_hh slice, layout [k][jl*4+g]
    float* h_s    = w_s + 512 * W_STRIDE;      // [64][H_STRIDE]  : h chunk, layout [k][b]
    float* wih_s  = h_s + 64 * H_STRIDE;       // [64] : [jl*4+g]
    float* bias_s = wih_s + 64;                // [64] : b_ih + b_hh folded
    __shared__ unsigned s_base;

    const int tid = threadIdx.x;
    const int tx  = tid & 15;    // local hidden unit j
    const int ty  = tid >> 4;    // batch group (0..31), owns 4 rows
    const int bi  = blockIdx.x >> 5;   // 0..3
    const int ji  = blockIdx.x & 31;   // 0..31
    const int b0  = bi * BS;
    const int j0  = ji * JS;

    if (tid == 0) s_base = g_gen;  // stable: no block can bump g_gen before all arrive at barrier 0

    // Load W_hh slice into SMEM once; kept resident for all 512 steps.
    for (int idx = tid; idx < 64 * 512; idx += NTHR) {
        int rr = idx >> 9;          // 0..63 = g*16 + jl
        int k  = idx & 511;
        int g  = rr >> 4;
        int jl = rr & 15;
        w_s[k * W_STRIDE + jl * 4 + g] = Whh[(size_t)(g * Hn + j0 + jl) * Hn + k];
    }
    if (tid < 64) {
        int jl = tid >> 2, g = tid & 3;
        int row = g * Hn + j0 + jl;
        wih_s[jl * 4 + g]  = Wih[row];
        bias_s[jl * 4 + g] = bih[row] + bhh[row];
    }

    // Zero h0 (buffer 0) and transpose sequence -> g_seqT[t][b] (coalesced reads)
    {
        float* h0p = &g_h[0][0][0];
        int base = blockIdx.x * 2048;
        #pragma unroll
        for (int i = 0; i < 4; ++i) {
            int idx = base + i * NTHR + tid;
            h0p[idx] = 0.0f;
            int b = idx >> 9, t = idx & 511;
            g_seqT[t][b] = seq[idx];           // seq is [b][t][1]
        }
    }
    grid_sync(s_base + 1);
    const unsigned base_gen = s_base;

    float c0 = 0.f, c1 = 0.f, c2 = 0.f, c3 = 0.f;   // cell state lives in registers

    for (int t = 0; t < Tn; ++t) {
        const float* hbuf = &g_h[t & 1][0][0];
        float* hout       = &g_h[(t & 1) ^ 1][0][0];

        float4 sv = *(const float4*)&g_seqT[t][b0 + ty * 4];
        float4 wi = *(const float4*)&wih_s[tx * 4];
        float4 bb = *(const float4*)&bias_s[tx * 4];

        // acc[r][g]: r = batch row in group, g = gate (i,f,g,o)
        float a00 = fmaf(sv.x, wi.x, bb.x), a01 = fmaf(sv.x, wi.y, bb.y),
              a02 = fmaf(sv.x, wi.z, bb.z), a03 = fmaf(sv.x, wi.w, bb.w);
        float a10 = fmaf(sv.y, wi.x, bb.x), a11 = fmaf(sv.y, wi.y, bb.y),
              a12 = fmaf(sv.y, wi.z, bb.z), a13 = fmaf(sv.y, wi.w, bb.w);
        float a20 = fmaf(sv.z, wi.x, bb.x), a21 = fmaf(sv.z, wi.y, bb.y),
              a22 = fmaf(sv.z, wi.z, bb.z), a23 = fmaf(sv.z, wi.w, bb.w);
        float a30 = fmaf(sv.w, wi.x, bb.x), a31 = fmaf(sv.w, wi.y, bb.y),
              a32 = fmaf(sv.w, wi.z, bb.z), a33 = fmaf(sv.w, wi.w, bb.w);

        #pragma unroll 1
        for (int kc = 0; kc < 8; ++kc) {
            __syncthreads();
            // Stage h chunk [64 k][128 b]; reads coalesced, SMEM writes conflict-free
            #pragma unroll
            for (int i = 0; i < 16; ++i) {
                int idx = i * NTHR + tid;
                int k = idx >> 7, b = idx & 127;
                h_s[k * H_STRIDE + b] = hbuf[(size_t)(kc * 64 + k) * Bn + b0 + b];
            }
            __syncthreads();

            const float* wp = w_s + (kc * 64) * W_STRIDE + tx * 4;
            const float* hp = h_s + ty * 4;
            #pragma unroll 8
            for (int k = 0; k < 64; ++k) {
                float4 w  = *(const float4*)(wp + k * W_STRIDE);
                float4 hv = *(const float4*)(hp + k * H_STRIDE);
                a00 = fmaf(hv.x, w.x, a00); a01 = fmaf(hv.x, w.y, a01);
                a02 = fmaf(hv.x, w.z, a02); a03 = fmaf(hv.x, w.w, a03);
                a10 = fmaf(hv.y, w.x, a10); a11 = fmaf(hv.y, w.y, a11);
                a12 = fmaf(hv.y, w.z, a12); a13 = fmaf(hv.y, w.w, a13);
                a20 = fmaf(hv.z, w.x, a20); a21 = fmaf(hv.z, w.y, a21);
                a22 = fmaf(hv.z, w.z, a22); a23 = fmaf(hv.z, w.w, a23);
                a30 = fmaf(hv.w, w.x, a30); a31 = fmaf(hv.w, w.y, a31);
                a32 = fmaf(hv.w, w.z, a32); a33 = fmaf(hv.w, w.w, a33);
            }
        }

        // LSTM cell (PyTorch gate order i,f,g,o)
        c0 = sigf(a01) * c0 + sigf(a00) * tanhf(a02);
        c1 = sigf(a11) * c1 + sigf(a10) * tanhf(a12);
        c2 = sigf(a21) * c2 + sigf(a20) * tanhf(a22);
        c3 = sigf(a31) * c3 + sigf(a30) * tanhf(a32);
        float4 ho;
        ho.x = sigf(a03) * tanhf(c0);
        ho.y = sigf(a13) * tanhf(c1);
        ho.z = sigf(a23) * tanhf(c2);
        ho.w = sigf(a33) * tanhf(c3);
        *(float4*)&hout[(size_t)(j0 + tx) * Bn + b0 + ty * 4] = ho;

        grid_sync(base_gen + 2 + t);
    }
    // Final h (t=511 writes buffer 0) consumed by mlp_head.
}

__global__ __launch_bounds__(256)
void mlp_head(const float* __restrict__ fc1w, const float* __restrict__ fc1b,
              const float* __restrict__ fc2w, const float* __restrict__ fc2b,
              float* __restrict__ out)
{
    __shared__ float hcol[512];
    __shared__ float z[256];
    const int b = blockIdx.x;
    const int tid = threadIdx.x;

    hcol[tid]       = g_h[0][tid][b];
    hcol[tid + 256] = g_h[0][tid + 256][b];
    __syncthreads();

    float acc = fc1b[tid];
    const float4* w4 = (const float4*)(fc1w + (size_t)tid * 512);
    const float4* h4 = (const float4*)hcol;
    #pragma unroll 4
    for (int k = 0; k < 128; ++k) {
        float4 w = w4[k], h = h4[k];
        acc = fmaf(w.x, h.x, acc); acc = fmaf(w.y, h.y, acc);
        acc = fmaf(w.z, h.z, acc); acc = fmaf(w.w, h.w, acc);
    }
    z[tid] = fmaxf(acc, 0.0f);
    __syncthreads();

    if (tid < 28) {
        float o = fc2b[tid];
        const float4* w4b = (const float4*)(fc2w + (size_t)tid * 256);
        const float4* z4  = (const float4*)z;
        #pragma unroll 4
        for (int k = 0; k < 64; ++k) {
            float4 w = w4b[k], zz = z4[k];
            o = fmaf(w.x, zz.x, o); o = fmaf(w.y, zz.y, o);
            o = fmaf(w.z, zz.z, o); o = fmaf(w.w, zz.w, o);
        }
        out[b * 28 + tid] = o;
    }
}

extern "C" void kernel_launch(void* const* d_in, const int* in_sizes, int n_in,
                              void* d_out, int out_size) {
    const float* seq  = (const float*)d_in[0];
    const float* Wih  = (const float*)d_in[1];
    const float* Whh  = (const float*)d_in[2];
    const float* bih  = (const float*)d_in[3];
    const float* bhh  = (const float*)d_in[4];
    const float* fc1w = (const float*)d_in[5];
    const float* fc1b = (const float*)d_in[6];
    const float* fc2w = (const float*)d_in[7];
    const float* fc2b = (const float*)d_in[8];
    float* out = (float*)d_out;

    size_t smem_bytes = (size_t)(512 * W_STRIDE + 64 * H_STRIDE + 128) * sizeof(float);
    cudaFuncSetAttribute(lstm_persistent, cudaFuncAttributeMaxDynamicSharedMemorySize,
                         (int)smem_bytes);

    lstm_persistent<<<NBLK, NTHR, smem_bytes>>>(seq, Wih, Whh, bih, bhh);
    mlp_head<<<Bn, 256>>>(fc1w, fc1b, fc2w, fc2b, out);
}

// round 5
// speedup vs baseline: 2.2583x; 2.2583x over previous
#include <cuda_runtime.h>
#include <cuda_bf16.h>
#include <math.h>
#include <stdint.h>

#define Bn 512
#define Tn 512
#define NBLK 128
#define NTHR 512

// ---- dynamic SMEM layout (bytes) ----
#define OFF_HHI(b) ((b) * 32768)            // h_hi chunk buf: 128 rows x 128B (SW128)
#define OFF_HLO(b) ((b) * 32768 + 16384)    // h_lo chunk buf
#define OFF_WHI    65536                    // W_hi tile: 512 k-rows x 128B (SW128) = 64KB
#define OFF_WLO    131072                   // W_lo tile = 64KB
#define OFF_WIH    196608                   // 64 floats
#define OFF_BIAS   196864                   // 64 floats
#define SMEM_BYTES 197120
// epilogue bounce regions (reuse chunk buffers, free at that point)
#define BOUNCE_HH  0                        // 128x16 bf16 = 4KB
#define BOUNCE_HL  4096                     // 4KB
#define BOUNCE_HF  16384                    // 128x16 f32 = 8KB (final step only)

static __device__ __forceinline__ uint32_t sw128(uint32_t x) { return x ^ ((x >> 3) & 0x70); }

// ---- global scratch (no cudaMalloc allowed) ----
__device__ __nv_bfloat16 g_hh[2][Bn][512];   // h hi, ping-pong, [batch][hidden]
__device__ __nv_bfloat16 g_hl[2][Bn][512];   // h lo
__device__ float g_seqT[Tn][Bn];
__device__ float g_hf[Bn][512];              // final fp32 h for MLP head
__device__ unsigned g_count = 0;
__device__ volatile unsigned g_gen = 0;

__device__ __forceinline__ uint32_t smem_u32(const void* p) {
    uint32_t a;
    asm("{ .reg .u64 t; cvta.to.shared.u64 t, %1; cvt.u32.u64 %0, t; }" : "=r"(a) : "l"(p));
    return a;
}
__device__ __forceinline__ void ldsm_x4(uint32_t* r, uint32_t addr) {
    asm volatile("ldmatrix.sync.aligned.m8n8.x4.shared.b16 {%0,%1,%2,%3}, [%4];"
                 : "=r"(r[0]), "=r"(r[1]), "=r"(r[2]), "=r"(r[3]) : "r"(addr));
}
__device__ __forceinline__ void ldsm_x4_t(uint32_t* r, uint32_t addr) {
    asm volatile("ldmatrix.sync.aligned.m8n8.x4.trans.shared.b16 {%0,%1,%2,%3}, [%4];"
                 : "=r"(r[0]), "=r"(r[1]), "=r"(r[2]), "=r"(r[3]) : "r"(addr));
}
__device__ __forceinline__ void mma_bf16(float* d, const uint32_t* a, const uint32_t* b) {
    asm volatile(
        "mma.sync.aligned.m16n8k16.row.col.f32.bf16.bf16.f32 "
        "{%0,%1,%2,%3}, {%4,%5,%6,%7}, {%8,%9}, {%0,%1,%2,%3};"
        : "+f"(d[0]), "+f"(d[1]), "+f"(d[2]), "+f"(d[3])
        : "r"(a[0]), "r"(a[1]), "r"(a[2]), "r"(a[3]), "r"(b[0]), "r"(b[1]));
}

__device__ __forceinline__ void grid_sync(unsigned target) {
    __syncthreads();
    if (threadIdx.x == 0) {
        __threadfence();
        unsigned old = atomicAdd(&g_count, 1u);
        if (old == NBLK - 1) {
            g_count = 0;
            __threadfence();
            g_gen = target;
        } else {
            while (g_gen != target) { }
            __threadfence();
        }
    }
    __syncthreads();
}

__device__ __forceinline__ float sigf(float x) { return 1.0f / (1.0f + expf(-x)); }

__global__ __launch_bounds__(NTHR, 1)
void lstm_tc(const float* __restrict__ seq,
             const float* __restrict__ Wih,
             const float* __restrict__ Whh,
             const float* __restrict__ bih,
             const float* __restrict__ bhh)
{
    extern __shared__ char smem[];
    __shared__ unsigned s_base;
    const uint32_t sb = smem_u32(smem);
    const int tid  = threadIdx.x;
    const int w    = tid >> 5;
    const int lane = tid & 31;
    const int bi   = blockIdx.x >> 5;   // batch tile 0..3
    const int ji   = blockIdx.x & 31;   // hidden-slice tile 0..31 (16 units each)
    const int b0   = bi * 128;
    const int j0   = ji * 16;

    if (tid == 0) s_base = g_gen;

    // ---- W_hh tile -> SMEM, bf16 hi/lo, k-major [k][n], SW128 swizzle ----
    // local col n = jl*4+g  <->  global W row = g*512 + j0 + jl
    for (int idx = tid; idx < 64 * 512; idx += NTHR) {
        int n = idx >> 9, k = idx & 511;
        int row = (n & 3) * 512 + j0 + (n >> 2);
        float wv = Whh[(size_t)row * 512 + k];
        __nv_bfloat16 whi = __float2bfloat16(wv);
        __nv_bfloat16 wlo = __float2bfloat16(wv - __bfloat162float(whi));
        uint32_t so = sw128((uint32_t)k * 128 + n * 2);
        *(__nv_bfloat16*)(smem + OFF_WHI + so) = whi;
        *(__nv_bfloat16*)(smem + OFF_WLO + so) = wlo;
    }
    if (tid < 64) {
        int jl = tid >> 2, g = tid & 3;
        int row = g * 512 + j0 + jl;
        ((float*)(smem + OFF_WIH))[tid]  = Wih[row];
        ((float*)(smem + OFF_BIAS))[tid] = bih[row] + bhh[row];
    }
    // zero h0 (buffer 0) and transpose sequence
    {
        int base = blockIdx.x * 2048;
        #pragma unroll
        for (int i = 0; i < 4; ++i) {
            int idx = base + i * NTHR + tid;
            ((__nv_bfloat16*)g_hh)[idx] = __float2bfloat16(0.0f);
            ((__nv_bfloat16*)g_hl)[idx] = __float2bfloat16(0.0f);
            int b = idx >> 9, t = idx & 511;
            g_seqT[t][b] = seq[idx];
        }
    }
    grid_sync(s_base + 1);
    const unsigned base_gen = s_base;

    // ---- per-lane constants ----
    const int wm = w & 3;                // batch quadrant of warp
    const int wn = w >> 2;               // gate-col quadrant (16 cols)
    // ldmatrix lane addressing: row offset lane&15, 16B-block lane>>4
    const int l15 = lane & 15;
    const int lb  = lane >> 4;
    // A: rows = batch (within 128-row chunk buffer)
    const uint32_t a_row  = (uint32_t)(wm * 32 + l15);
    const uint32_t a_xm   = a_row & 7;                   // swizzle mask /16
    const uint32_t a_base = sb + a_row * 128;            // + OFF_HHI(buf) + mt*2048 + col16*16
    // B: rows = k (512-row W tile)
    const uint32_t b_col16 = (uint32_t)(((wn * 2 + lb) ^ (l15 & 7)));
    const uint32_t b_base  = sb + OFF_WHI + (uint32_t)l15 * 128 + b_col16 * 16;

    // staging offsets (same as fp32 version)
    const int sm_r = tid >> 2, sq = tid & 3;
    const uint32_t sts_off  = sw128((uint32_t)sm_r * 128 + sq * 32);
    const uint32_t sts_off2 = sw128((uint32_t)sm_r * 128 + sq * 32 + 16);

    // epilogue per-lane constants: 4 gate-cols ca(nt), cb(nt)
    const float* wih_s  = (const float*)(smem + OFF_WIH);
    const float* bias_s = (const float*)(smem + OFF_BIAS);
    float bw_a[2], bw_b[2], wi_a[2], wi_b[2];
    #pragma unroll
    for (int nt = 0; nt < 2; ++nt) {
        int ca = wn * 16 + nt * 8 + (lane & 3) * 2;
        bw_a[nt] = bias_s[ca];     bw_b[nt] = bias_s[ca + 1];
        wi_a[nt] = wih_s[ca];      wi_b[nt] = wih_s[ca + 1];
    }
    const int q = lane & 1;                       // 0: lane computes rowA; 1: rowB
    const int rowm0 = wm * 32 + (lane >> 2);      // mt=0 rowA (local)
    float cst[4] = {0.f, 0.f, 0.f, 0.f};

    // prefetch chunk 0 of step 0
    uint4 phh0, phh1, phl0, phl1;
    {
        const uint4* ph = (const uint4*)&g_hh[0][b0 + sm_r][sq * 16];
        const uint4* pl = (const uint4*)&g_hl[0][b0 + sm_r][sq * 16];
        phh0 = ph[0]; phh1 = ph[1]; phl0 = pl[0]; phl1 = pl[1];
    }

    for (int t = 0; t < Tn; ++t) {
        const int rb = t & 1, nb = rb ^ 1;

        // init accumulators with bias + x*W_ih (mma accumulates on top)
        float acc[2][2][4];
        #pragma unroll
        for (int mt = 0; mt < 2; ++mt) {
            float svA = g_seqT[t][b0 + rowm0 + mt * 16];
            float svB = g_seqT[t][b0 + rowm0 + mt * 16 + 8];
            #pragma unroll
            for (int nt = 0; nt < 2; ++nt) {
                acc[mt][nt][0] = fmaf(svA, wi_a[nt], bw_a[nt]);
                acc[mt][nt][1] = fmaf(svA, wi_b[nt], bw_b[nt]);
                acc[mt][nt][2] = fmaf(svB, wi_a[nt], bw_a[nt]);
                acc[mt][nt][3] = fmaf(svB, wi_b[nt], bw_b[nt]);
            }
        }

        #pragma unroll 1
        for (int kc = 0; kc < 8; ++kc) {
            const int buf = kc & 1;
            __syncthreads();   // all readers of this buf (kc-2) are done
            *(uint4*)(smem + OFF_HHI(buf) + sts_off)  = phh0;
            *(uint4*)(smem + OFF_HHI(buf) + sts_off2) = phh1;
            *(uint4*)(smem + OFF_HLO(buf) + sts_off)  = phl0;
            *(uint4*)(smem + OFF_HLO(buf) + sts_off2) = phl1;
            if (kc < 7) {   // prefetch next chunk (overlaps compute below)
                const uint4* ph = (const uint4*)&g_hh[rb][b0 + sm_r][(kc + 1) * 64 + sq * 16];
                const uint4* pl = (const uint4*)&g_hl[rb][b0 + sm_r][(kc + 1) * 64 + sq * 16];
                phh0 = ph[0]; phh1 = ph[1]; phl0 = pl[0]; phl1 = pl[1];
            }
            __syncthreads();   // staging visible

            const uint32_t abuf = a_base + OFF_HHI(buf);
            const uint32_t bk   = b_base + (uint32_t)kc * 8192;
            #pragma unroll
            for (int kq = 0; kq < 4; ++kq) {
                const uint32_t acol = (uint32_t)(((kq * 2 + lb) ^ a_xm)) << 4;
                uint32_t ah0[4], ah1[4], al0[4], al1[4], bh[4], bl[4];
                ldsm_x4(ah0, abuf + acol);                    // A hi, mt=0
                ldsm_x4(ah1, abuf + 2048 + acol);             // A hi, mt=1
                ldsm_x4(al0, abuf + 16384 + acol);            // A lo, mt=0
                ldsm_x4(al1, abuf + 16384 + 2048 + acol);     // A lo, mt=1
                ldsm_x4_t(bh, bk + (uint32_t)kq * 2048);      // B hi (k16 x n16)
                ldsm_x4_t(bl, bk + (uint32_t)kq * 2048 + 65536); // B lo
                // 12 HMMA: hi*hi + lo*hi + hi*lo
                mma_bf16(acc[0][0], ah0, bh);     mma_bf16(acc[0][1], ah0, bh + 2);
                mma_bf16(acc[1][0], ah1, bh);     mma_bf16(acc[1][1], ah1, bh + 2);
                mma_bf16(acc[0][0], al0, bh);     mma_bf16(acc[0][1], al0, bh + 2);
                mma_bf16(acc[1][0], al1, bh);     mma_bf16(acc[1][1], al1, bh + 2);
                mma_bf16(acc[0][0], ah0, bl);     mma_bf16(acc[0][1], ah0, bl + 2);
                mma_bf16(acc[1][0], ah1, bl);     mma_bf16(acc[1][1], ah1, bl + 2);
            }
        }

        __syncthreads();   // chunk buffers free -> safe to reuse as bounce

        // ---- LSTM cell epilogue: lane pairs exchange (i,f)<->(g,o) ----
        #pragma unroll
        for (int mt = 0; mt < 2; ++mt) {
            #pragma unroll
            for (int nt = 0; nt < 2; ++nt) {
                float x0 = __shfl_xor_sync(0xffffffffu, acc[mt][nt][0], 1);
                float x1 = __shfl_xor_sync(0xffffffffu, acc[mt][nt][1], 1);
                float x2 = __shfl_xor_sync(0xffffffffu, acc[mt][nt][2], 1);
                float x3 = __shfl_xor_sync(0xffffffffu, acc[mt][nt][3], 1);
                float gi, gf, gg, go;
                int rowl;
                if (q == 0) { gi = acc[mt][nt][0]; gf = acc[mt][nt][1]; gg = x0; go = x1;
                              rowl = rowm0 + mt * 16; }
                else        { gi = x2; gf = x3; gg = acc[mt][nt][2]; go = acc[mt][nt][3];
                              rowl = rowm0 + mt * 16 + 8; }
                const int ci = mt * 2 + nt;
                cst[ci] = sigf(gf) * cst[ci] + sigf(gi) * tanhf(gg);
                float h = sigf(go) * tanhf(cst[ci]);
                int ul = wn * 4 + nt * 2 + ((lane & 3) >> 1);   // local unit 0..15
                __nv_bfloat16 hhi = __float2bfloat16(h);
                __nv_bfloat16 hlo = __float2bfloat16(h - __bfloat162float(hhi));
                *(__nv_bfloat16*)(smem + BOUNCE_HH + rowl * 32 + ul * 2) = hhi;
                *(__nv_bfloat16*)(smem + BOUNCE_HL + rowl * 32 + ul * 2) = hlo;
                if (t == Tn - 1)
                    *(float*)(smem + BOUNCE_HF + rowl * 64 + ul * 4) = h;
            }
        }
        __syncthreads();
        // coalesced write-out of this CTA's 128x16 h slice
        {
            unsigned long long hv = *(unsigned long long*)(smem + BOUNCE_HH + sm_r * 32 + sq * 8);
            unsigned long long lv = *(unsigned long long*)(smem + BOUNCE_HL + sm_r * 32 + sq * 8);
            *(unsigned long long*)&g_hh[nb][b0 + sm_r][j0 + sq * 4] = hv;
            *(unsigned long long*)&g_hl[nb][b0 + sm_r][j0 + sq * 4] = lv;
            if (t == Tn - 1) {
                float4 f4 = *(float4*)(smem + BOUNCE_HF + sm_r * 64 + sq * 16);
                *(float4*)&g_hf[b0 + sm_r][j0 + sq * 4] = f4;
            }
        }
        grid_sync(base_gen + 2 + t);

        // prefetch chunk 0 of next step (globally visible after barrier)
        if (t + 1 < Tn) {
            const uint4* ph = (const uint4*)&g_hh[nb][b0 + sm_r][sq * 16];
            const uint4* pl = (const uint4*)&g_hl[nb][b0 + sm_r][sq * 16];
            phh0 = ph[0]; phh1 = ph[1]; phl0 = pl[0]; phl1 = pl[1];
        }
    }
}

__global__ __launch_bounds__(256)
void mlp_head(const float* __restrict__ fc1w, const float* __restrict__ fc1b,
              const float* __restrict__ fc2w, const float* __restrict__ fc2b,
              float* __restrict__ out)
{
    __shared__ float hcol[512];
    __shared__ float z[256];
    const int b = blockIdx.x;
    const int tid = threadIdx.x;

    hcol[tid]       = g_hf[b][tid];
    hcol[tid + 256] = g_hf[b][tid + 256];
    __syncthreads();

    float acc = fc1b[tid];
    const float4* w4 = (const float4*)(fc1w + (size_t)tid * 512);
    const float4* h4 = (const float4*)hcol;
    #pragma unroll 4
    for (int k = 0; k < 128; ++k) {
        float4 wv = w4[k], hv = h4[k];
        acc = fmaf(wv.x, hv.x, acc); acc = fmaf(wv.y, hv.y, acc);
        acc = fmaf(wv.z, hv.z, acc); acc = fmaf(wv.w, hv.w, acc);
    }
    z[tid] = fmaxf(acc, 0.0f);
    __syncthreads();

    if (tid < 28) {
        float o = fc2b[tid];
        const float4* w4b = (const float4*)(fc2w + (size_t)tid * 256);
        const float4* z4  = (const float4*)z;
        #pragma unroll 4
        for (int k = 0; k < 64; ++k) {
            float4 wv = w4b[k], zz = z4[k];
            o = fmaf(wv.x, zz.x, o); o = fmaf(wv.y, zz.y, o);
            o = fmaf(wv.z, zz.z, o); o = fmaf(wv.w, zz.w, o);
        }
        out[b * 28 + tid] = o;
    }
}

extern "C" void kernel_launch(void* const* d_in, const int* in_sizes, int n_in,
                              void* d_out, int out_size) {
    const float* seq  = (const float*)d_in[0];
    const float* Wih  = (const float*)d_in[1];
    const float* Whh  = (const float*)d_in[2];
    const float* bih  = (const float*)d_in[3];
    const float* bhh  = (const float*)d_in[4];
    const float* fc1w = (const float*)d_in[5];
    const float* fc1b = (const float*)d_in[6];
    const float* fc2w = (const float*)d_in[7];
    const float* fc2b = (const float*)d_in[8];
    float* out = (float*)d_out;

    cudaFuncSetAttribute(lstm_tc, cudaFuncAttributeMaxDynamicSharedMemorySize, SMEM_BYTES);
    lstm_tc<<<NBLK, NTHR, SMEM_BYTES>>>(seq, Wih, Whh, bih, bhh);
    mlp_head<<<Bn, 256>>>(fc1w, fc1b, fc2w, fc2b, out);
}